// round 12
// baseline (speedup 1.0000x reference)
#include <cuda_runtime.h>
#include <cuda_bf16.h>
#include <cuda_fp16.h>
#include <cstdint>
#include <math.h>

#define NB 16
#define NT 512
#define NH 1024
#define NL 8192
#define ND 256

typedef unsigned int u32;

// ---- attn operands: single fp16, mma.sync fragment order ----
__device__ uint4 g_Qf[NL * ND / 8];
__device__ uint4 g_Wf[NL * ND / 8];
__device__ uint2 g_Kf[NB * NT * ND / 4];
__device__ uint2 g_Vf[NB * NT * ND / 4];

// ---- kv-gemm operands (bf16 3-term split) ----
__device__ uint4 g_Xh[NB * NT * NH / 8];
__device__ uint4 g_Xl[NB * NT * NH / 8];
__device__ uint2 g_Wkh[ND * NH / 4];
__device__ uint2 g_Wkl[ND * NH / 4];
__device__ uint2 g_Wvh[ND * NH / 4];
__device__ uint2 g_Wvl[ND * NH / 4];

__device__ __forceinline__ void mma_bf16(float* c, const uint4& a, const uint2& b) {
    asm("mma.sync.aligned.m16n8k16.row.col.f32.bf16.bf16.f32 "
        "{%0,%1,%2,%3}, {%4,%5,%6,%7}, {%8,%9}, {%0,%1,%2,%3};"
        : "+f"(c[0]), "+f"(c[1]), "+f"(c[2]), "+f"(c[3])
        : "r"(a.x), "r"(a.y), "r"(a.z), "r"(a.w), "r"(b.x), "r"(b.y));
}
__device__ __forceinline__ void mma_f16(float* c, const uint4& a, const uint2& b) {
    asm("mma.sync.aligned.m16n8k16.row.col.f32.f16.f16.f32 "
        "{%0,%1,%2,%3}, {%4,%5,%6,%7}, {%8,%9}, {%0,%1,%2,%3};"
        : "+f"(c[0]), "+f"(c[1]), "+f"(c[2]), "+f"(c[3])
        : "r"(a.x), "r"(a.y), "r"(a.z), "r"(a.w), "r"(b.x), "r"(b.y));
}
__device__ __forceinline__ u32 bf16pair(float x0, float x1) {
    __nv_bfloat162 h = __floats2bfloat162_rn(x0, x1);
    return *(u32*)&h;
}
__device__ __forceinline__ u32 h2pair(float x0, float x1) {
    __half2 h = __floats2half2_rn(x0, x1);
    return *(u32*)&h;
}
__device__ __forceinline__ u32 smem_u32(const void* p) {
    u32 a; asm("{ .reg .u64 t; cvta.to.shared.u64 t, %1; cvt.u32.u64 %0, t; }" : "=r"(a) : "l"(p));
    return a;
}
__device__ __forceinline__ void cpasync16(u32 dst, const void* src) {
    asm volatile("cp.async.cg.shared.global [%0], [%1], 16;" :: "r"(dst), "l"(src));
}
#define CP_COMMIT() asm volatile("cp.async.commit_group;" ::: "memory")
#define CP_WAIT0()  asm volatile("cp.async.wait_group 0;" ::: "memory")
#define CP_WAIT1()  asm volatile("cp.async.wait_group 1;" ::: "memory")

__device__ __forceinline__ void split_store(u32* dh, u32* dl, size_t idx, float x0, float x1) {
    __nv_bfloat16 h0 = __float2bfloat16(x0);
    __nv_bfloat16 h1 = __float2bfloat16(x1);
    dh[idx] = (u32)__bfloat16_as_ushort(h0) | ((u32)__bfloat16_as_ushort(h1) << 16);
    dl[idx] = bf16pair(x0 - __bfloat162float(h0), x1 - __bfloat162float(h1));
}

// ---------------------------------------------------------------------------
// split_x: X fp32 -> Xh/Xl bf16 A-frag order, smem-staged (proven)
// ---------------------------------------------------------------------------
__global__ __launch_bounds__(256, 1) void split_x(const float* __restrict__ X) {
    extern __shared__ u32 s[];
    u32* sxh = s;
    u32* sxl = s + 8192;
    const int mt  = blockIdx.x;
    const int tid = threadIdx.x;

#pragma unroll 4
    for (int it = 0; it < 16; it++) {
        int i  = tid + it * 256;
        int r  = i >> 8;
        int c4 = i & 255;
        float4 x = *(const float4*)&X[((size_t)mt * 16 + r) * NH + c4 * 4];
        float xa[4] = {x.x, x.y, x.z, x.w};
        int rh = r >> 3, lane_lo = (r & 7) * 4;
#pragma unroll
        for (int p = 0; p < 2; p++) {
            int d = c4 * 4 + p * 2;
            int kt = d >> 4, kd = d & 15;
            int lane = lane_lo + ((kd >> 1) & 3);
            int idx = (kt * 32 + lane) * 4 + ((kd >> 3) * 2 + rh);
            split_store(sxh, sxl, idx, xa[p * 2], xa[p * 2 + 1]);
        }
    }
    __syncthreads();
    uint4* oh = g_Xh + (size_t)mt * 2048;
    uint4* ol = g_Xl + (size_t)mt * 2048;
    const uint4* s4h = (const uint4*)sxh;
    const uint4* s4l = (const uint4*)sxl;
#pragma unroll
    for (int it = 0; it < 8; it++) {
        oh[tid + it * 256] = s4h[tid + it * 256];
        ol[tid + it * 256] = s4l[tid + it * 256];
    }
}

// ---------------------------------------------------------------------------
// split_qw: queries (scale folded) / out_weight -> single fp16 A-frags, staged
// ---------------------------------------------------------------------------
__global__ __launch_bounds__(256, 1) void split_qw(
    const float* __restrict__ Q, const float* __restrict__ W)
{
    __shared__ u32 s[2 * 2048];
    const int mt  = blockIdx.x;
    const int tid = threadIdx.x;
    const float sc = 0.0625f;

#pragma unroll 2
    for (int it = 0; it < 4; it++) {
        int i  = tid + it * 256;
        int r  = i >> 6;
        int c4 = i & 63;
        float4 q = *(const float4*)&Q[((size_t)mt * 16 + r) * ND + c4 * 4];
        float4 w = *(const float4*)&W[((size_t)mt * 16 + r) * ND + c4 * 4];
        float qa[4] = {q.x * sc, q.y * sc, q.z * sc, q.w * sc};
        float wa[4] = {w.x, w.y, w.z, w.w};
        int rh = r >> 3, lane_lo = (r & 7) * 4;
#pragma unroll
        for (int p = 0; p < 2; p++) {
            int d = c4 * 4 + p * 2;
            int kt = d >> 4, kd = d & 15;
            int lane = lane_lo + ((kd >> 1) & 3);
            int idx = (kt * 32 + lane) * 4 + ((kd >> 3) * 2 + rh);
            s[idx]        = h2pair(qa[p * 2], qa[p * 2 + 1]);
            s[2048 + idx] = h2pair(wa[p * 2], wa[p * 2 + 1]);
        }
    }
    __syncthreads();
    const uint4* s4 = (const uint4*)s;
    uint4* oq = g_Qf + (size_t)mt * 512;
    uint4* ow = g_Wf + (size_t)mt * 512;
    oq[tid]       = s4[tid];
    oq[tid + 256] = s4[tid + 256];
    ow[tid]       = s4[512 + tid];
    ow[tid + 256] = s4[512 + tid + 256];
}

// ---------------------------------------------------------------------------
// split_w: Wk/Wv fp32 [256,1024] -> bf16 hi/lo B-frag order
// ---------------------------------------------------------------------------
__global__ void split_w(const float* __restrict__ Wk, const float* __restrict__ Wv) {
    int i = blockIdx.x * blockDim.x + threadIdx.x;
    if (i >= ND * NH / 4) return;
    const float* src = blockIdx.y ? Wv : Wk;
    u32* dh = (u32*)(blockIdx.y ? g_Wvh : g_Wkh);
    u32* dl = (u32*)(blockIdx.y ? g_Wvl : g_Wkl);
    int d  = i >> 8;
    int h0 = (i & 255) * 4;
    float4 x = ((const float4*)src)[i];
    float xa[4] = {x.x, x.y, x.z, x.w};
    int nt = d >> 3, nr = d & 7;
#pragma unroll
    for (int p = 0; p < 2; p++) {
        int h  = h0 + p * 2;
        int kt = h >> 4, kd = h & 15;
        int lane = nr * 4 + ((kd >> 1) & 3);
        size_t idx = (((size_t)nt * 64 + kt) * 32 + lane) * 2 + (kd >> 3);
        split_store(dh, dl, idx, xa[p * 2], xa[p * 2 + 1]);
    }
}

// ---------------------------------------------------------------------------
// kv_mma: unchanged (85us proven). bf16 3-term, 2kt/stage.
// ---------------------------------------------------------------------------
__global__ __launch_bounds__(512, 1) void kv_mma(int dummy) {
    extern __shared__ __align__(16) char dsm[];
    const int tid  = threadIdx.x;
    const int lane = tid & 31;
    const int w    = tid >> 5;
    const int wm   = w >> 1;
    const int wt   = w & 1;
    const int ng   = blockIdx.y;
    const int isV  = ng >> 1;
    const int nhalf = ng & 1;
    const u32 smb  = smem_u32(dsm);

    const uint2* Bh = isV ? g_Wvh : g_Wkh;
    const uint2* Bl = isV ? g_Wvl : g_Wkl;
    u32* dst = (u32*)(isV ? g_Vf : g_Kf);

    const size_t aRow = (size_t)blockIdx.x * 8;
    const size_t ntBase = (size_t)nhalf * 16;

    const int grp = tid >> 7;
    const int gi  = tid & 127;

    float acc[32];
#pragma unroll
    for (int x = 0; x < 32; x++) acc[x] = 0.f;

    auto loadStage = [&](int buf, int kt0) {
#pragma unroll
        for (int s = 0; s < 2; s++) {
            int kt = kt0 + s;
            u32 base = smb + buf * 32768 + s * 16384;
            if (grp < 2) {
                const uint4* src = grp ? g_Xl : g_Xh;
                u32 abase = base + grp * 4096;
#pragma unroll
                for (int e = 0; e < 2; e++) {
                    int el = gi + e * 128;
                    int mt = el >> 5, ln = el & 31;
                    cpasync16(abase + el * 16, src + ((aRow + mt) * 64 + kt) * 32 + ln);
                }
            } else {
                const uint4* src = (const uint4*)((grp == 2) ? Bh : Bl);
                u32 bbase = base + 8192 + (grp - 2) * 4096;
#pragma unroll
                for (int e = 0; e < 2; e++) {
                    int el = gi + e * 128;
                    int nt = el >> 4, lp = el & 15;
                    cpasync16(bbase + el * 16, src + ((ntBase + nt) * 64 + kt) * 16 + lp);
                }
            }
        }
        CP_COMMIT();
    };

    loadStage(0, 0);
    CP_WAIT0();
    __syncthreads();

    for (int st = 0; st < 32; st++) {
        const int buf = st & 1;
        if (st < 31) loadStage(buf ^ 1, (st + 1) * 2);
#pragma unroll
        for (int s = 0; s < 2; s++) {
            const char* sb = dsm + buf * 32768 + s * 16384;
            uint4 xh = *(const uint4*)(sb +        (wm * 32 + lane) * 16);
            uint4 xl = *(const uint4*)(sb + 4096 + (wm * 32 + lane) * 16);
            const char* bb = sb + 8192;
#pragma unroll
            for (int j = 0; j < 8; j++) {
                int nt = wt * 8 + j;
                uint2 wh = *(const uint2*)(bb +        (nt * 32 + lane) * 8);
                uint2 wl = *(const uint2*)(bb + 4096 + (nt * 32 + lane) * 8);
                mma_bf16(&acc[j * 4], xh, wh);
                mma_bf16(&acc[j * 4], xh, wl);
                mma_bf16(&acc[j * 4], xl, wh);
            }
        }
        if (st < 31) CP_WAIT0();
        __syncthreads();
    }

#pragma unroll
    for (int j = 0; j < 8; j++) {
        int d  = nhalf * 128 + wt * 64 + j * 8 + (lane & 3) * 2;
        int kt = d >> 4, kd = d & 15;
        int lane_lo = (kd >> 1) & 3;
#pragma unroll
        for (int h = 0; h < 2; h++) {
            int bt = blockIdx.x * 128 + wm * 16 + (lane >> 2) + h * 8;
            int bb2 = bt >> 9, t = bt & 511;
            int nt = t >> 3, rt = t & 7;
            size_t idx = ((((size_t)bb2 * 64 + nt) * 16 + kt) * 32 + rt * 4 + lane_lo) * 2 + (kd >> 3);
            dst[idx] = h2pair(acc[j * 4 + h * 2], acc[j * 4 + h * 2 + 1]);
        }
    }
}

// ---------------------------------------------------------------------------
// attn: fused dual-GEMM flash attention, single fp16.
// 256 threads, warp = 4mt x 4nt. 3-stage ring (96KB), wait_group 1
// (one full stage of fill slack), issue-before-compute, and warp-staggered
// slab order within each stage to desynchronize SMSP LDS bursts.
// ---------------------------------------------------------------------------
__global__ __launch_bounds__(256, 1) void attn_kernel(
    const float* __restrict__ bias,
    const int*   __restrict__ mask,
    float*       __restrict__ out)
{
    extern __shared__ __align__(16) char dsm[];
    __shared__ int   smask[NT];
    __shared__ float sM[4][128], sD[4][128], sN[4][128];

    const int tid  = threadIdx.x;
    const int lane = tid & 31;
    const int w    = tid >> 5;
    const int wi   = w >> 2;    // 0..1, 4 mt each
    const int wj   = w & 3;     // 0..3, 4 nt each
    const int l0   = blockIdx.x * 128;
    const int b    = blockIdx.y;
    const u32 smb  = smem_u32(dsm);

    smask[tid]       = mask[b * NT + tid];
    smask[tid + 256] = mask[b * NT + tid + 256];

    const size_t aRow = (size_t)blockIdx.x * 8;

    // producer: one stage = 2 kt slabs of 16KB (Qf 0 | Wf 4096 | Kf 8192 | Vf 12288)
    auto loadStage = [&](int st) {
        u32 sbase = smb + (st % 3) * 32768;
#pragma unroll
        for (int s = 0; s < 2; s++) {
            int g  = st * 2 + s;
            int kt = g & 15;
            size_t bRow = (size_t)b * 64 + (g >> 4) * 16;
            u32 base = sbase + s * 16384;
#pragma unroll
            for (int r = 0; r < 4; r++) {
                int idx = tid + r * 256;       // 0..1023 uint4 within slab
                if (idx < 512) {
                    int arr = idx >> 8, el = idx & 255;
                    int mt = el >> 5, ln = el & 31;
                    const uint4* src = arr ? g_Wf : g_Qf;
                    cpasync16(base + idx * 16,
                              src + ((aRow + mt) * 16 + kt) * 32 + ln);
                } else {
                    int i2 = idx - 512;
                    int arr = i2 >> 8, be = i2 & 255;
                    int nt = be >> 4, lp = be & 15;
                    const uint4* src = (const uint4*)(arr ? g_Vf : g_Kf);
                    cpasync16(base + 8192 + i2 * 16,
                              src + ((bRow + nt) * 16 + kt) * 16 + lp);
                }
            }
        }
        CP_COMMIT();
    };

    float S[64], U[64];
#pragma unroll
    for (int x = 0; x < 64; x++) { S[x] = 0.f; U[x] = 0.f; }
    float mrun[8], dnr[8], nmr[8];
#pragma unroll
    for (int x = 0; x < 8; x++) { mrun[x] = -1e30f; dnr[x] = 0.f; nmr[x] = 0.f; }

    loadStage(0);
    loadStage(1);

    for (int st = 0; st < 32; st++) {
        if (st < 31) CP_WAIT1(); else CP_WAIT0();
        __syncthreads();            // stage st resident; slab (st%3) free for reuse
        if (st < 30) loadStage(st + 2);

        const u32 sbase = smb + (st % 3) * 32768;
#pragma unroll
        for (int ss = 0; ss < 2; ss++) {
            const int s = ss ^ (w & 1);            // stagger slab order per warp
            const char* sb = (const char*)dsm + ((st % 3) * 32768 + s * 16384);
            (void)sbase;
            uint4 qf[4], wf[4];
#pragma unroll
            for (int m = 0; m < 4; m++) {
                int mt = wi * 4 + m;
                qf[m] = *(const uint4*)(sb +        (mt * 32 + lane) * 16);
                wf[m] = *(const uint4*)(sb + 4096 + (mt * 32 + lane) * 16);
            }
#pragma unroll
            for (int j = 0; j < 4; j++) {
                int nt = wj * 4 + j;
                uint2 kf = *(const uint2*)(sb + 8192  + (nt * 32 + lane) * 8);
                uint2 vf = *(const uint2*)(sb + 12288 + (nt * 32 + lane) * 8);
#pragma unroll
                for (int m = 0; m < 4; m++) {
                    mma_f16(&S[(m * 4 + j) * 4], qf[m], kf);
                    mma_f16(&U[(m * 4 + j) * 4], wf[m], vf);
                }
            }
        }

        if ((st & 7) == 7) {
            // chunk epilogue (stage boundary == chunk boundary: 8 stages = 16 kt)
            const int chunk = st >> 3;
            const int cb = chunk * 128 + wj * 32 + (lane & 3) * 2;
#pragma unroll
            for (int m = 0; m < 4; m++) {
#pragma unroll
                for (int h = 0; h < 2; h++) {
                    int stx = m * 2 + h;
                    float mloc = -1e30f;
                    int   mk[8];
                    float sv[8];
#pragma unroll
                    for (int j = 0; j < 4; j++)
#pragma unroll
                        for (int e = 0; e < 2; e++) {
                            int ix = j * 2 + e;
                            mk[ix] = smask[cb + j * 8 + e];
                            sv[ix] = S[(m * 4 + j) * 4 + h * 2 + e];
                            if (mk[ix]) mloc = fmaxf(mloc, sv[ix]);
                        }
                    mloc = fmaxf(mloc, __shfl_xor_sync(0xFFFFFFFFu, mloc, 1));
                    mloc = fmaxf(mloc, __shfl_xor_sync(0xFFFFFFFFu, mloc, 2));
                    float newm = fmaxf(mrun[stx], mloc);
                    float f = __expf(mrun[stx] - newm);
                    float ds = 0.f, ns = 0.f;
#pragma unroll
                    for (int j = 0; j < 4; j++)
#pragma unroll
                        for (int e = 0; e < 2; e++) {
                            int ix = j * 2 + e;
                            float p = mk[ix] ? __expf(sv[ix] - newm) : 0.f;
                            ds += p;
                            ns += p * U[(m * 4 + j) * 4 + h * 2 + e];
                        }
                    ds += __shfl_xor_sync(0xFFFFFFFFu, ds, 1);
                    ds += __shfl_xor_sync(0xFFFFFFFFu, ds, 2);
                    ns += __shfl_xor_sync(0xFFFFFFFFu, ns, 1);
                    ns += __shfl_xor_sync(0xFFFFFFFFu, ns, 2);
                    dnr[stx] = dnr[stx] * f + ds;
                    nmr[stx] = nmr[stx] * f + ns;
                    mrun[stx] = newm;
                }
            }
#pragma unroll
            for (int x = 0; x < 64; x++) { S[x] = 0.f; U[x] = 0.f; }
        }
    }

    // merge the 4 wj partials per row
    __syncthreads();
    if ((lane & 3) == 0) {
#pragma unroll
        for (int m = 0; m < 4; m++)
#pragma unroll
            for (int h = 0; h < 2; h++) {
                int rl = (wi * 4 + m) * 16 + (lane >> 2) + h * 8;
                int stx = m * 2 + h;
                sM[wj][rl] = mrun[stx];
                sD[wj][rl] = dnr[stx];
                sN[wj][rl] = nmr[stx];
            }
    }
    __syncthreads();
    if (tid < 128) {
        float mm = -1e30f;
#pragma unroll
        for (int c = 0; c < 4; c++) mm = fmaxf(mm, sM[c][tid]);
        float dn = 0.f, nm = 0.f;
#pragma unroll
        for (int c = 0; c < 4; c++) {
            float f = __expf(sM[c][tid] - mm);
            dn += sD[c][tid] * f;
            nm += sN[c][tid] * f;
        }
        out[b * NL + l0 + tid] = nm / dn + bias[l0 + tid];
    }
}

extern "C" void kernel_launch(void* const* d_in, const int* in_sizes, int n_in,
                              void* d_out, int out_size) {
    const float* X       = (const float*)d_in[0];
    const int*   mask    = (const int*)  d_in[1];
    const float* queries = (const float*)d_in[2];
    const float* Wk      = (const float*)d_in[3];
    const float* Wv      = (const float*)d_in[4];
    const float* outw    = (const float*)d_in[5];
    const float* bias    = (const float*)d_in[6];
    float* out = (float*)d_out;

    cudaFuncSetAttribute(split_x, cudaFuncAttributeMaxDynamicSharedMemorySize, 65536);
    split_x<<<512, 256, 65536>>>(X);
    dim3 gw((ND * NH / 4 + 255) / 256, 2);
    split_w<<<gw, 256>>>(Wk, Wv);
    split_qw<<<512, 256>>>(queries, outw);

    cudaFuncSetAttribute(kv_mma, cudaFuncAttributeMaxDynamicSharedMemorySize, 65536);
    dim3 g1(64, 4);
    kv_mma<<<g1, 512, 65536>>>(0);

    cudaFuncSetAttribute(attn_kernel, cudaFuncAttributeMaxDynamicSharedMemorySize, 98304);
    dim3 g2(64, 16);
    attn_kernel<<<g2, 256, 98304>>>(bias, mask, out);
}

// round 13
// speedup vs baseline: 1.1302x; 1.1302x over previous
#include <cuda_runtime.h>
#include <cuda_bf16.h>
#include <cuda_fp16.h>
#include <cstdint>
#include <math.h>

#define NB 16
#define NT 512
#define NH 1024
#define NL 8192
#define ND 256

typedef unsigned int u32;

// ---- attn operands: single fp16, mma.sync fragment order ----
__device__ uint4 g_Qf[NL * ND / 8];
__device__ uint4 g_Wf[NL * ND / 8];
__device__ uint2 g_Kf[NB * NT * ND / 4];
__device__ uint2 g_Vf[NB * NT * ND / 4];

// ---- kv-gemm operands (bf16 3-term split) ----
__device__ uint4 g_Xh[NB * NT * NH / 8];
__device__ uint4 g_Xl[NB * NT * NH / 8];
__device__ uint2 g_Wkh[ND * NH / 4];
__device__ uint2 g_Wkl[ND * NH / 4];
__device__ uint2 g_Wvh[ND * NH / 4];
__device__ uint2 g_Wvl[ND * NH / 4];

__device__ __forceinline__ void mma_bf16(float* c, const uint4& a, const uint2& b) {
    asm("mma.sync.aligned.m16n8k16.row.col.f32.bf16.bf16.f32 "
        "{%0,%1,%2,%3}, {%4,%5,%6,%7}, {%8,%9}, {%0,%1,%2,%3};"
        : "+f"(c[0]), "+f"(c[1]), "+f"(c[2]), "+f"(c[3])
        : "r"(a.x), "r"(a.y), "r"(a.z), "r"(a.w), "r"(b.x), "r"(b.y));
}
__device__ __forceinline__ void mma_f16(float* c, const uint4& a, const uint2& b) {
    asm("mma.sync.aligned.m16n8k16.row.col.f32.f16.f16.f32 "
        "{%0,%1,%2,%3}, {%4,%5,%6,%7}, {%8,%9}, {%0,%1,%2,%3};"
        : "+f"(c[0]), "+f"(c[1]), "+f"(c[2]), "+f"(c[3])
        : "r"(a.x), "r"(a.y), "r"(a.z), "r"(a.w), "r"(b.x), "r"(b.y));
}
__device__ __forceinline__ u32 bf16pair(float x0, float x1) {
    __nv_bfloat162 h = __floats2bfloat162_rn(x0, x1);
    return *(u32*)&h;
}
__device__ __forceinline__ u32 h2pair(float x0, float x1) {
    __half2 h = __floats2half2_rn(x0, x1);
    return *(u32*)&h;
}
__device__ __forceinline__ u32 smem_u32(const void* p) {
    u32 a; asm("{ .reg .u64 t; cvta.to.shared.u64 t, %1; cvt.u32.u64 %0, t; }" : "=r"(a) : "l"(p));
    return a;
}
__device__ __forceinline__ void cpasync16(u32 dst, const void* src) {
    asm volatile("cp.async.cg.shared.global [%0], [%1], 16;" :: "r"(dst), "l"(src));
}
#define CP_COMMIT() asm volatile("cp.async.commit_group;" ::: "memory")
#define CP_WAIT0()  asm volatile("cp.async.wait_group 0;" ::: "memory")

__device__ __forceinline__ void split_store(u32* dh, u32* dl, size_t idx, float x0, float x1) {
    __nv_bfloat16 h0 = __float2bfloat16(x0);
    __nv_bfloat16 h1 = __float2bfloat16(x1);
    dh[idx] = (u32)__bfloat16_as_ushort(h0) | ((u32)__bfloat16_as_ushort(h1) << 16);
    dl[idx] = bf16pair(x0 - __bfloat162float(h0), x1 - __bfloat162float(h1));
}

// ---------------------------------------------------------------------------
// split_x: X fp32 -> Xh/Xl bf16 A-frag order, smem-staged (proven)
// ---------------------------------------------------------------------------
__global__ __launch_bounds__(256, 1) void split_x(const float* __restrict__ X) {
    extern __shared__ u32 s[];
    u32* sxh = s;
    u32* sxl = s + 8192;
    const int mt  = blockIdx.x;
    const int tid = threadIdx.x;

#pragma unroll 4
    for (int it = 0; it < 16; it++) {
        int i  = tid + it * 256;
        int r  = i >> 8;
        int c4 = i & 255;
        float4 x = *(const float4*)&X[((size_t)mt * 16 + r) * NH + c4 * 4];
        float xa[4] = {x.x, x.y, x.z, x.w};
        int rh = r >> 3, lane_lo = (r & 7) * 4;
#pragma unroll
        for (int p = 0; p < 2; p++) {
            int d = c4 * 4 + p * 2;
            int kt = d >> 4, kd = d & 15;
            int lane = lane_lo + ((kd >> 1) & 3);
            int idx = (kt * 32 + lane) * 4 + ((kd >> 3) * 2 + rh);
            split_store(sxh, sxl, idx, xa[p * 2], xa[p * 2 + 1]);
        }
    }
    __syncthreads();
    uint4* oh = g_Xh + (size_t)mt * 2048;
    uint4* ol = g_Xl + (size_t)mt * 2048;
    const uint4* s4h = (const uint4*)sxh;
    const uint4* s4l = (const uint4*)sxl;
#pragma unroll
    for (int it = 0; it < 8; it++) {
        oh[tid + it * 256] = s4h[tid + it * 256];
        ol[tid + it * 256] = s4l[tid + it * 256];
    }
}

// ---------------------------------------------------------------------------
// split_qw: queries (scale folded) / out_weight -> single fp16 A-frags, staged
// ---------------------------------------------------------------------------
__global__ __launch_bounds__(256, 1) void split_qw(
    const float* __restrict__ Q, const float* __restrict__ W)
{
    __shared__ u32 s[2 * 2048];
    const int mt  = blockIdx.x;
    const int tid = threadIdx.x;
    const float sc = 0.0625f;

#pragma unroll 2
    for (int it = 0; it < 4; it++) {
        int i  = tid + it * 256;
        int r  = i >> 6;
        int c4 = i & 63;
        float4 q = *(const float4*)&Q[((size_t)mt * 16 + r) * ND + c4 * 4];
        float4 w = *(const float4*)&W[((size_t)mt * 16 + r) * ND + c4 * 4];
        float qa[4] = {q.x * sc, q.y * sc, q.z * sc, q.w * sc};
        float wa[4] = {w.x, w.y, w.z, w.w};
        int rh = r >> 3, lane_lo = (r & 7) * 4;
#pragma unroll
        for (int p = 0; p < 2; p++) {
            int d = c4 * 4 + p * 2;
            int kt = d >> 4, kd = d & 15;
            int lane = lane_lo + ((kd >> 1) & 3);
            int idx = (kt * 32 + lane) * 4 + ((kd >> 3) * 2 + rh);
            s[idx]        = h2pair(qa[p * 2], qa[p * 2 + 1]);
            s[2048 + idx] = h2pair(wa[p * 2], wa[p * 2 + 1]);
        }
    }
    __syncthreads();
    const uint4* s4 = (const uint4*)s;
    uint4* oq = g_Qf + (size_t)mt * 512;
    uint4* ow = g_Wf + (size_t)mt * 512;
    oq[tid]       = s4[tid];
    oq[tid + 256] = s4[tid + 256];
    ow[tid]       = s4[512 + tid];
    ow[tid + 256] = s4[512 + tid + 256];
}

// ---------------------------------------------------------------------------
// split_w: Wk/Wv fp32 [256,1024] -> bf16 hi/lo B-frag order
// ---------------------------------------------------------------------------
__global__ void split_w(const float* __restrict__ Wk, const float* __restrict__ Wv) {
    int i = blockIdx.x * blockDim.x + threadIdx.x;
    if (i >= ND * NH / 4) return;
    const float* src = blockIdx.y ? Wv : Wk;
    u32* dh = (u32*)(blockIdx.y ? g_Wvh : g_Wkh);
    u32* dl = (u32*)(blockIdx.y ? g_Wvl : g_Wkl);
    int d  = i >> 8;
    int h0 = (i & 255) * 4;
    float4 x = ((const float4*)src)[i];
    float xa[4] = {x.x, x.y, x.z, x.w};
    int nt = d >> 3, nr = d & 7;
#pragma unroll
    for (int p = 0; p < 2; p++) {
        int h  = h0 + p * 2;
        int kt = h >> 4, kd = h & 15;
        int lane = nr * 4 + ((kd >> 1) & 3);
        size_t idx = (((size_t)nt * 64 + kt) * 32 + lane) * 2 + (kd >> 3);
        split_store(dh, dl, idx, xa[p * 2], xa[p * 2 + 1]);
    }
}

// ---------------------------------------------------------------------------
// kv_mma: unchanged (85us, at its HMMA issue floor). bf16 3-term, 2kt/stage.
// ---------------------------------------------------------------------------
__global__ __launch_bounds__(512, 1) void kv_mma(int dummy) {
    extern __shared__ __align__(16) char dsm[];
    const int tid  = threadIdx.x;
    const int lane = tid & 31;
    const int w    = tid >> 5;
    const int wm   = w >> 1;
    const int wt   = w & 1;
    const int ng   = blockIdx.y;
    const int isV  = ng >> 1;
    const int nhalf = ng & 1;
    const u32 smb  = smem_u32(dsm);

    const uint2* Bh = isV ? g_Wvh : g_Wkh;
    const uint2* Bl = isV ? g_Wvl : g_Wkl;
    u32* dst = (u32*)(isV ? g_Vf : g_Kf);

    const size_t aRow = (size_t)blockIdx.x * 8;
    const size_t ntBase = (size_t)nhalf * 16;

    const int grp = tid >> 7;
    const int gi  = tid & 127;

    float acc[32];
#pragma unroll
    for (int x = 0; x < 32; x++) acc[x] = 0.f;

    auto loadStage = [&](int buf, int kt0) {
#pragma unroll
        for (int s = 0; s < 2; s++) {
            int kt = kt0 + s;
            u32 base = smb + buf * 32768 + s * 16384;
            if (grp < 2) {
                const uint4* src = grp ? g_Xl : g_Xh;
                u32 abase = base + grp * 4096;
#pragma unroll
                for (int e = 0; e < 2; e++) {
                    int el = gi + e * 128;
                    int mt = el >> 5, ln = el & 31;
                    cpasync16(abase + el * 16, src + ((aRow + mt) * 64 + kt) * 32 + ln);
                }
            } else {
                const uint4* src = (const uint4*)((grp == 2) ? Bh : Bl);
                u32 bbase = base + 8192 + (grp - 2) * 4096;
#pragma unroll
                for (int e = 0; e < 2; e++) {
                    int el = gi + e * 128;
                    int nt = el >> 4, lp = el & 15;
                    cpasync16(bbase + el * 16, src + ((ntBase + nt) * 64 + kt) * 16 + lp);
                }
            }
        }
        CP_COMMIT();
    };

    loadStage(0, 0);
    CP_WAIT0();
    __syncthreads();

    for (int st = 0; st < 32; st++) {
        const int buf = st & 1;
        if (st < 31) loadStage(buf ^ 1, (st + 1) * 2);
#pragma unroll
        for (int s = 0; s < 2; s++) {
            const char* sb = dsm + buf * 32768 + s * 16384;
            uint4 xh = *(const uint4*)(sb +        (wm * 32 + lane) * 16);
            uint4 xl = *(const uint4*)(sb + 4096 + (wm * 32 + lane) * 16);
            const char* bb = sb + 8192;
#pragma unroll
            for (int j = 0; j < 8; j++) {
                int nt = wt * 8 + j;
                uint2 wh = *(const uint2*)(bb +        (nt * 32 + lane) * 8);
                uint2 wl = *(const uint2*)(bb + 4096 + (nt * 32 + lane) * 8);
                mma_bf16(&acc[j * 4], xh, wh);
                mma_bf16(&acc[j * 4], xh, wl);
                mma_bf16(&acc[j * 4], xl, wh);
            }
        }
        if (st < 31) CP_WAIT0();
        __syncthreads();
    }

#pragma unroll
    for (int j = 0; j < 8; j++) {
        int d  = nhalf * 128 + wt * 64 + j * 8 + (lane & 3) * 2;
        int kt = d >> 4, kd = d & 15;
        int lane_lo = (kd >> 1) & 3;
#pragma unroll
        for (int h = 0; h < 2; h++) {
            int bt = blockIdx.x * 128 + wm * 16 + (lane >> 2) + h * 8;
            int bb2 = bt >> 9, t = bt & 511;
            int nt = t >> 3, rt = t & 7;
            size_t idx = ((((size_t)bb2 * 64 + nt) * 16 + kt) * 32 + rt * 4 + lane_lo) * 2 + (kd >> 3);
            dst[idx] = h2pair(acc[j * 4 + h * 2], acc[j * 4 + h * 2 + 1]);
        }
    }
}

// ---------------------------------------------------------------------------
// attn: fused dual-GEMM flash attention, single fp16, OCCUPANCY 2.
// CTA tile = 64 labels x 128 T. grid (128, 16). 256 threads, 8 warps:
// wi = w>>2 (2 mt each), wj = w&3 (4 nt each). Warp tile 2mt x 4nt.
// Double buffer, 2 kt/stage, 12KB slabs (Qf 0|Wf 2048|Kf 4096|Vf 8192).
// 48KB dyn smem -> 2 CTAs/SM fill each other's issue bubbles.
// ---------------------------------------------------------------------------
__global__ __launch_bounds__(256, 2) void attn_kernel(
    const float* __restrict__ bias,
    const int*   __restrict__ mask,
    float*       __restrict__ out)
{
    extern __shared__ __align__(16) char dsm[];
    __shared__ int   smask[NT];
    __shared__ float sM[4][64], sD[4][64], sN[4][64];

    const int tid  = threadIdx.x;
    const int lane = tid & 31;
    const int w    = tid >> 5;
    const int wi   = w >> 2;    // 0..1, 2 mt each
    const int wj   = w & 3;     // 0..3, 4 nt each
    const int l0   = blockIdx.x * 64;
    const int b    = blockIdx.y;
    const u32 smb  = smem_u32(dsm);

    smask[tid]       = mask[b * NT + tid];
    smask[tid + 256] = mask[b * NT + tid + 256];

    const size_t aRow = (size_t)blockIdx.x * 4;   // mt base (4 mt per CTA)

    // producer: one stage = 2 slabs of 12KB; 768 uint4 per slab, 3 rounds of 256
    auto loadStage = [&](int buf, int g0) {
#pragma unroll
        for (int s = 0; s < 2; s++) {
            int g  = g0 + s;
            int kt = g & 15;
            size_t bRow = (size_t)b * 64 + (g >> 4) * 16;
            u32 base = smb + buf * 24576 + s * 12288;
#pragma unroll
            for (int r = 0; r < 3; r++) {
                int idx = tid + r * 256;       // 0..767 uint4 within slab
                if (idx < 256) {
                    int arr = idx >> 7, el = idx & 127;   // 0=Qf 1=Wf
                    int mt = el >> 5, ln = el & 31;
                    const uint4* src = arr ? g_Wf : g_Qf;
                    cpasync16(base + idx * 16,
                              src + ((aRow + mt) * 16 + kt) * 32 + ln);
                } else {
                    int i2 = idx - 256;                    // 0..511
                    int arr = i2 >> 8, be = i2 & 255;      // 0=Kf 1=Vf
                    int nt = be >> 4, lp = be & 15;
                    const uint4* src = (const uint4*)(arr ? g_Vf : g_Kf);
                    cpasync16(base + 4096 + i2 * 16,
                              src + ((bRow + nt) * 16 + kt) * 16 + lp);
                }
            }
        }
        CP_COMMIT();
    };

    float S[32], U[32];                 // [(m*4+j)*4 + c], m in 0..1
#pragma unroll
    for (int x = 0; x < 32; x++) { S[x] = 0.f; U[x] = 0.f; }
    float mrun[4], dnr[4], nmr[4];      // [m*2+h]
#pragma unroll
    for (int x = 0; x < 4; x++) { mrun[x] = -1e30f; dnr[x] = 0.f; nmr[x] = 0.f; }

    loadStage(0, 0);
    CP_WAIT0();
    __syncthreads();

    for (int st = 0; st < 32; st++) {
        const int buf = st & 1;
        if (st < 31) loadStage(buf ^ 1, (st + 1) * 2);
#pragma unroll
        for (int s = 0; s < 2; s++) {
            const int g = st * 2 + s;
            const char* sb = dsm + buf * 24576 + s * 12288;
            uint4 qf[2], wf[2];
#pragma unroll
            for (int m = 0; m < 2; m++) {
                int mt = wi * 2 + m;
                qf[m] = *(const uint4*)(sb +        (mt * 32 + lane) * 16);
                wf[m] = *(const uint4*)(sb + 2048 + (mt * 32 + lane) * 16);
            }
#pragma unroll
            for (int j = 0; j < 4; j++) {
                int nt = wj * 4 + j;
                uint2 kf = *(const uint2*)(sb + 4096 + (nt * 32 + lane) * 8);
                uint2 vf = *(const uint2*)(sb + 8192 + (nt * 32 + lane) * 8);
#pragma unroll
                for (int m = 0; m < 2; m++) {
                    mma_f16(&S[(m * 4 + j) * 4], qf[m], kf);
                    mma_f16(&U[(m * 4 + j) * 4], wf[m], vf);
                }
            }

            if ((g & 15) == 15) {
                const int chunk = g >> 4;
                const int cb = chunk * 128 + wj * 32 + (lane & 3) * 2;
#pragma unroll
                for (int m = 0; m < 2; m++) {
#pragma unroll
                    for (int h = 0; h < 2; h++) {
                        int stx = m * 2 + h;
                        float mloc = -1e30f;
                        int   mk[8];
                        float sv[8];
#pragma unroll
                        for (int j = 0; j < 4; j++)
#pragma unroll
                            for (int e = 0; e < 2; e++) {
                                int ix = j * 2 + e;
                                mk[ix] = smask[cb + j * 8 + e];
                                sv[ix] = S[(m * 4 + j) * 4 + h * 2 + e];
                                if (mk[ix]) mloc = fmaxf(mloc, sv[ix]);
                            }
                        mloc = fmaxf(mloc, __shfl_xor_sync(0xFFFFFFFFu, mloc, 1));
                        mloc = fmaxf(mloc, __shfl_xor_sync(0xFFFFFFFFu, mloc, 2));
                        float newm = fmaxf(mrun[stx], mloc);
                        float f = __expf(mrun[stx] - newm);
                        float ds = 0.f, ns = 0.f;
#pragma unroll
                        for (int j = 0; j < 4; j++)
#pragma unroll
                            for (int e = 0; e < 2; e++) {
                                int ix = j * 2 + e;
                                float p = mk[ix] ? __expf(sv[ix] - newm) : 0.f;
                                ds += p;
                                ns += p * U[(m * 4 + j) * 4 + h * 2 + e];
                            }
                        ds += __shfl_xor_sync(0xFFFFFFFFu, ds, 1);
                        ds += __shfl_xor_sync(0xFFFFFFFFu, ds, 2);
                        ns += __shfl_xor_sync(0xFFFFFFFFu, ns, 1);
                        ns += __shfl_xor_sync(0xFFFFFFFFu, ns, 2);
                        dnr[stx] = dnr[stx] * f + ds;
                        nmr[stx] = nmr[stx] * f + ns;
                        mrun[stx] = newm;
                    }
                }
#pragma unroll
                for (int x = 0; x < 32; x++) { S[x] = 0.f; U[x] = 0.f; }
            }
        }
        if (st < 31) CP_WAIT0();
        __syncthreads();
    }

    // merge the 4 wj partials per row (64 rows)
    if ((lane & 3) == 0) {
#pragma unroll
        for (int m = 0; m < 2; m++)
#pragma unroll
            for (int h = 0; h < 2; h++) {
                int rl = (wi * 2 + m) * 16 + (lane >> 2) + h * 8;
                int stx = m * 2 + h;
                sM[wj][rl] = mrun[stx];
                sD[wj][rl] = dnr[stx];
                sN[wj][rl] = nmr[stx];
            }
    }
    __syncthreads();
    if (tid < 64) {
        float mm = -1e30f;
#pragma unroll
        for (int c = 0; c < 4; c++) mm = fmaxf(mm, sM[c][tid]);
        float dn = 0.f, nm = 0.f;
#pragma unroll
        for (int c = 0; c < 4; c++) {
            float f = __expf(sM[c][tid] - mm);
            dn += sD[c][tid] * f;
            nm += sN[c][tid] * f;
        }
        out[b * NL + l0 + tid] = nm / dn + bias[l0 + tid];
    }
}

extern "C" void kernel_launch(void* const* d_in, const int* in_sizes, int n_in,
                              void* d_out, int out_size) {
    const float* X       = (const float*)d_in[0];
    const int*   mask    = (const int*)  d_in[1];
    const float* queries = (const float*)d_in[2];
    const float* Wk      = (const float*)d_in[3];
    const float* Wv      = (const float*)d_in[4];
    const float* outw    = (const float*)d_in[5];
    const float* bias    = (const float*)d_in[6];
    float* out = (float*)d_out;

    cudaFuncSetAttribute(split_x, cudaFuncAttributeMaxDynamicSharedMemorySize, 65536);
    split_x<<<512, 256, 65536>>>(X);
    dim3 gw((ND * NH / 4 + 255) / 256, 2);
    split_w<<<gw, 256>>>(Wk, Wv);
    split_qw<<<512, 256>>>(queries, outw);

    cudaFuncSetAttribute(kv_mma, cudaFuncAttributeMaxDynamicSharedMemorySize, 65536);
    dim3 g1(64, 4);
    kv_mma<<<g1, 512, 65536>>>(0);

    cudaFuncSetAttribute(attn_kernel, cudaFuncAttributeMaxDynamicSharedMemorySize, 49152);
    dim3 g2(128, 16);
    attn_kernel<<<g2, 256, 49152>>>(bias, mask, out);
}

// round 14
// speedup vs baseline: 1.3197x; 1.1677x over previous
#include <cuda_runtime.h>
#include <cuda_bf16.h>
#include <cuda_fp16.h>
#include <cstdint>
#include <math.h>

#define NB 16
#define NT 512
#define NH 1024
#define NL 8192
#define ND 256

typedef unsigned int u32;

// ---- attn operands: single fp16, mma.sync fragment order ----
__device__ uint4 g_Qf[NL * ND / 8];
__device__ uint4 g_Wf[NL * ND / 8];
__device__ uint2 g_Kf[NB * NT * ND / 4];
__device__ uint2 g_Vf[NB * NT * ND / 4];

// ---- kv-gemm operands: single fp16 ----
// X A-frag: [mt(512)][kt(64)][lane(32)] uint4
__device__ uint4 g_Xf[NB * NT * NH / 8];
// W B-frag: [nt(32)][kt(64)][lane(32)] uint2
__device__ uint2 g_Wkf[ND * NH / 4];
__device__ uint2 g_Wvf[ND * NH / 4];

__device__ __forceinline__ void mma_f16(float* c, const uint4& a, const uint2& b) {
    asm("mma.sync.aligned.m16n8k16.row.col.f32.f16.f16.f32 "
        "{%0,%1,%2,%3}, {%4,%5,%6,%7}, {%8,%9}, {%0,%1,%2,%3};"
        : "+f"(c[0]), "+f"(c[1]), "+f"(c[2]), "+f"(c[3])
        : "r"(a.x), "r"(a.y), "r"(a.z), "r"(a.w), "r"(b.x), "r"(b.y));
}
__device__ __forceinline__ u32 h2pair(float x0, float x1) {
    __half2 h = __floats2half2_rn(x0, x1);
    return *(u32*)&h;
}
__device__ __forceinline__ u32 smem_u32(const void* p) {
    u32 a; asm("{ .reg .u64 t; cvta.to.shared.u64 t, %1; cvt.u32.u64 %0, t; }" : "=r"(a) : "l"(p));
    return a;
}
__device__ __forceinline__ void cpasync16(u32 dst, const void* src) {
    asm volatile("cp.async.cg.shared.global [%0], [%1], 16;" :: "r"(dst), "l"(src));
}
#define CP_COMMIT() asm volatile("cp.async.commit_group;" ::: "memory")
#define CP_WAIT0()  asm volatile("cp.async.wait_group 0;" ::: "memory")

// ---------------------------------------------------------------------------
// split_x: X fp32 -> Xf single fp16 A-frag order, smem-staged.
// CTA = one mt (16 bt rows x 1024 cols). grid 512. 32KB dyn smem.
// ---------------------------------------------------------------------------
__global__ __launch_bounds__(256, 1) void split_x(const float* __restrict__ X) {
    extern __shared__ u32 s[];           // 8192 u32 = 32KB
    const int mt  = blockIdx.x;
    const int tid = threadIdx.x;

#pragma unroll 4
    for (int it = 0; it < 16; it++) {
        int i  = tid + it * 256;
        int r  = i >> 8;                 // row 0..15 (256 float4 per row)
        int c4 = i & 255;
        float4 x = *(const float4*)&X[((size_t)mt * 16 + r) * NH + c4 * 4];
        float xa[4] = {x.x, x.y, x.z, x.w};
        int rh = r >> 3, lane_lo = (r & 7) * 4;
#pragma unroll
        for (int p = 0; p < 2; p++) {
            int d = c4 * 4 + p * 2;
            int kt = d >> 4, kd = d & 15;
            int lane = lane_lo + ((kd >> 1) & 3);
            int idx = (kt * 32 + lane) * 4 + ((kd >> 3) * 2 + rh);
            s[idx] = h2pair(xa[p * 2], xa[p * 2 + 1]);
        }
    }
    __syncthreads();
    uint4* o = g_Xf + (size_t)mt * 2048;
    const uint4* s4 = (const uint4*)s;
#pragma unroll
    for (int it = 0; it < 8; it++)
        o[tid + it * 256] = s4[tid + it * 256];
}

// ---------------------------------------------------------------------------
// split_qw: queries (scale folded) / out_weight -> single fp16 A-frags, staged
// ---------------------------------------------------------------------------
__global__ __launch_bounds__(256, 1) void split_qw(
    const float* __restrict__ Q, const float* __restrict__ W)
{
    __shared__ u32 s[2 * 2048];
    const int mt  = blockIdx.x;
    const int tid = threadIdx.x;
    const float sc = 0.0625f;

#pragma unroll 2
    for (int it = 0; it < 4; it++) {
        int i  = tid + it * 256;
        int r  = i >> 6;
        int c4 = i & 63;
        float4 q = *(const float4*)&Q[((size_t)mt * 16 + r) * ND + c4 * 4];
        float4 w = *(const float4*)&W[((size_t)mt * 16 + r) * ND + c4 * 4];
        float qa[4] = {q.x * sc, q.y * sc, q.z * sc, q.w * sc};
        float wa[4] = {w.x, w.y, w.z, w.w};
        int rh = r >> 3, lane_lo = (r & 7) * 4;
#pragma unroll
        for (int p = 0; p < 2; p++) {
            int d = c4 * 4 + p * 2;
            int kt = d >> 4, kd = d & 15;
            int lane = lane_lo + ((kd >> 1) & 3);
            int idx = (kt * 32 + lane) * 4 + ((kd >> 3) * 2 + rh);
            s[idx]        = h2pair(qa[p * 2], qa[p * 2 + 1]);
            s[2048 + idx] = h2pair(wa[p * 2], wa[p * 2 + 1]);
        }
    }
    __syncthreads();
    const uint4* s4 = (const uint4*)s;
    uint4* oq = g_Qf + (size_t)mt * 512;
    uint4* ow = g_Wf + (size_t)mt * 512;
    oq[tid]       = s4[tid];
    oq[tid + 256] = s4[tid + 256];
    ow[tid]       = s4[512 + tid];
    ow[tid + 256] = s4[512 + tid + 256];
}

// ---------------------------------------------------------------------------
// split_w: Wk/Wv fp32 [256,1024] -> single fp16 B-frag order
// ---------------------------------------------------------------------------
__global__ void split_w(const float* __restrict__ Wk, const float* __restrict__ Wv) {
    int i = blockIdx.x * blockDim.x + threadIdx.x;
    if (i >= ND * NH / 4) return;
    const float* src = blockIdx.y ? Wv : Wk;
    u32* dst = (u32*)(blockIdx.y ? g_Wvf : g_Wkf);
    int d  = i >> 8;
    int h0 = (i & 255) * 4;
    float4 x = ((const float4*)src)[i];
    float xa[4] = {x.x, x.y, x.z, x.w};
    int nt = d >> 3, nr = d & 7;
#pragma unroll
    for (int p = 0; p < 2; p++) {
        int h  = h0 + p * 2;
        int kt = h >> 4, kd = h & 15;
        int lane = nr * 4 + ((kd >> 1) & 3);
        size_t idx = (((size_t)nt * 64 + kt) * 32 + lane) * 2 + (kd >> 3);
        dst[idx] = h2pair(xa[p * 2], xa[p * 2 + 1]);
    }
}

// ---------------------------------------------------------------------------
// kv_mma: K/V projection, SINGLE fp16 (3x fewer MMAs than bf16 3-term).
// grid (64,4): x = 128-row bt tile, y = ng. 512 threads. 32KB dyn smem.
// Slab per kt (8KB): Xf 0 (4KB) | Wf 4096 (4KB). 2 kt/stage, double buffer.
// ---------------------------------------------------------------------------
__global__ __launch_bounds__(512, 1) void kv_mma(int dummy) {
    extern __shared__ __align__(16) char dsm[];
    const int tid  = threadIdx.x;
    const int lane = tid & 31;
    const int w    = tid >> 5;
    const int wm   = w >> 1;
    const int wt   = w & 1;
    const int ng   = blockIdx.y;
    const int isV  = ng >> 1;
    const int nhalf = ng & 1;
    const u32 smb  = smem_u32(dsm);

    const uint4* Bsrc = (const uint4*)(isV ? g_Wvf : g_Wkf);
    u32* dst = (u32*)(isV ? g_Vf : g_Kf);

    const size_t aRow = (size_t)blockIdx.x * 8;
    const size_t ntBase = (size_t)nhalf * 16;

    float acc[32];
#pragma unroll
    for (int x = 0; x < 32; x++) acc[x] = 0.f;

    auto loadStage = [&](int buf, int kt0) {
#pragma unroll
        for (int s = 0; s < 2; s++) {
            int kt = kt0 + s;
            u32 base = smb + buf * 16384 + s * 8192;
            if (tid < 256) {
                int mt = tid >> 5, ln = tid & 31;
                cpasync16(base + tid * 16,
                          g_Xf + ((aRow + mt) * 64 + kt) * 32 + ln);
            } else {
                int i2 = tid - 256;
                int nt = i2 >> 4, lp = i2 & 15;
                cpasync16(base + 4096 + i2 * 16,
                          Bsrc + ((ntBase + nt) * 64 + kt) * 16 + lp);
            }
        }
        CP_COMMIT();
    };

    loadStage(0, 0);
    CP_WAIT0();
    __syncthreads();

    for (int st = 0; st < 32; st++) {
        const int buf = st & 1;
        if (st < 31) loadStage(buf ^ 1, (st + 1) * 2);
#pragma unroll
        for (int s = 0; s < 2; s++) {
            const char* sb = dsm + buf * 16384 + s * 8192;
            uint4 xf = *(const uint4*)(sb + (wm * 32 + lane) * 16);
            const char* bb = sb + 4096;
#pragma unroll
            for (int j = 0; j < 8; j++) {
                int nt = wt * 8 + j;
                uint2 wf = *(const uint2*)(bb + (nt * 32 + lane) * 8);
                mma_f16(&acc[j * 4], xf, wf);
            }
        }
        if (st < 31) CP_WAIT0();
        __syncthreads();
    }

    // epilogue: scatter fp16 pairs into attn B-frag layout
#pragma unroll
    for (int j = 0; j < 8; j++) {
        int d  = nhalf * 128 + wt * 64 + j * 8 + (lane & 3) * 2;
        int kt = d >> 4, kd = d & 15;
        int lane_lo = (kd >> 1) & 3;
#pragma unroll
        for (int h = 0; h < 2; h++) {
            int bt = blockIdx.x * 128 + wm * 16 + (lane >> 2) + h * 8;
            int bb2 = bt >> 9, t = bt & 511;
            int nt = t >> 3, rt = t & 7;
            size_t idx = ((((size_t)bb2 * 64 + nt) * 16 + kt) * 32 + rt * 4 + lane_lo) * 2 + (kd >> 3);
            dst[idx] = h2pair(acc[j * 4 + h * 2], acc[j * 4 + h * 2 + 1]);
        }
    }
}

// ---------------------------------------------------------------------------
// attn: unchanged from round 13 (occupancy 2, 64 labels x 128 T per CTA).
// ---------------------------------------------------------------------------
__global__ __launch_bounds__(256, 2) void attn_kernel(
    const float* __restrict__ bias,
    const int*   __restrict__ mask,
    float*       __restrict__ out)
{
    extern __shared__ __align__(16) char dsm[];
    __shared__ int   smask[NT];
    __shared__ float sM[4][64], sD[4][64], sN[4][64];

    const int tid  = threadIdx.x;
    const int lane = tid & 31;
    const int w    = tid >> 5;
    const int wi   = w >> 2;
    const int wj   = w & 3;
    const int l0   = blockIdx.x * 64;
    const int b    = blockIdx.y;
    const u32 smb  = smem_u32(dsm);

    smask[tid]       = mask[b * NT + tid];
    smask[tid + 256] = mask[b * NT + tid + 256];

    const size_t aRow = (size_t)blockIdx.x * 4;

    auto loadStage = [&](int buf, int g0) {
#pragma unroll
        for (int s = 0; s < 2; s++) {
            int g  = g0 + s;
            int kt = g & 15;
            size_t bRow = (size_t)b * 64 + (g >> 4) * 16;
            u32 base = smb + buf * 24576 + s * 12288;
#pragma unroll
            for (int r = 0; r < 3; r++) {
                int idx = tid + r * 256;
                if (idx < 256) {
                    int arr = idx >> 7, el = idx & 127;
                    int mt = el >> 5, ln = el & 31;
                    const uint4* src = arr ? g_Wf : g_Qf;
                    cpasync16(base + idx * 16,
                              src + ((aRow + mt) * 16 + kt) * 32 + ln);
                } else {
                    int i2 = idx - 256;
                    int arr = i2 >> 8, be = i2 & 255;
                    int nt = be >> 4, lp = be & 15;
                    const uint4* src = (const uint4*)(arr ? g_Vf : g_Kf);
                    cpasync16(base + 4096 + i2 * 16,
                              src + ((bRow + nt) * 16 + kt) * 16 + lp);
                }
            }
        }
        CP_COMMIT();
    };

    float S[32], U[32];
#pragma unroll
    for (int x = 0; x < 32; x++) { S[x] = 0.f; U[x] = 0.f; }
    float mrun[4], dnr[4], nmr[4];
#pragma unroll
    for (int x = 0; x < 4; x++) { mrun[x] = -1e30f; dnr[x] = 0.f; nmr[x] = 0.f; }

    loadStage(0, 0);
    CP_WAIT0();
    __syncthreads();

    for (int st = 0; st < 32; st++) {
        const int buf = st & 1;
        if (st < 31) loadStage(buf ^ 1, (st + 1) * 2);
#pragma unroll
        for (int s = 0; s < 2; s++) {
            const int g = st * 2 + s;
            const char* sb = dsm + buf * 24576 + s * 12288;
            uint4 qf[2], wf[2];
#pragma unroll
            for (int m = 0; m < 2; m++) {
                int mt = wi * 2 + m;
                qf[m] = *(const uint4*)(sb +        (mt * 32 + lane) * 16);
                wf[m] = *(const uint4*)(sb + 2048 + (mt * 32 + lane) * 16);
            }
#pragma unroll
            for (int j = 0; j < 4; j++) {
                int nt = wj * 4 + j;
                uint2 kf = *(const uint2*)(sb + 4096 + (nt * 32 + lane) * 8);
                uint2 vf = *(const uint2*)(sb + 8192 + (nt * 32 + lane) * 8);
#pragma unroll
                for (int m = 0; m < 2; m++) {
                    mma_f16(&S[(m * 4 + j) * 4], qf[m], kf);
                    mma_f16(&U[(m * 4 + j) * 4], wf[m], vf);
                }
            }

            if ((g & 15) == 15) {
                const int chunk = g >> 4;
                const int cb = chunk * 128 + wj * 32 + (lane & 3) * 2;
#pragma unroll
                for (int m = 0; m < 2; m++) {
#pragma unroll
                    for (int h = 0; h < 2; h++) {
                        int stx = m * 2 + h;
                        float mloc = -1e30f;
                        int   mk[8];
                        float sv[8];
#pragma unroll
                        for (int j = 0; j < 4; j++)
#pragma unroll
                            for (int e = 0; e < 2; e++) {
                                int ix = j * 2 + e;
                                mk[ix] = smask[cb + j * 8 + e];
                                sv[ix] = S[(m * 4 + j) * 4 + h * 2 + e];
                                if (mk[ix]) mloc = fmaxf(mloc, sv[ix]);
                            }
                        mloc = fmaxf(mloc, __shfl_xor_sync(0xFFFFFFFFu, mloc, 1));
                        mloc = fmaxf(mloc, __shfl_xor_sync(0xFFFFFFFFu, mloc, 2));
                        float newm = fmaxf(mrun[stx], mloc);
                        float f = __expf(mrun[stx] - newm);
                        float ds = 0.f, ns = 0.f;
#pragma unroll
                        for (int j = 0; j < 4; j++)
#pragma unroll
                            for (int e = 0; e < 2; e++) {
                                int ix = j * 2 + e;
                                float p = mk[ix] ? __expf(sv[ix] - newm) : 0.f;
                                ds += p;
                                ns += p * U[(m * 4 + j) * 4 + h * 2 + e];
                            }
                        ds += __shfl_xor_sync(0xFFFFFFFFu, ds, 1);
                        ds += __shfl_xor_sync(0xFFFFFFFFu, ds, 2);
                        ns += __shfl_xor_sync(0xFFFFFFFFu, ns, 1);
                        ns += __shfl_xor_sync(0xFFFFFFFFu, ns, 2);
                        dnr[stx] = dnr[stx] * f + ds;
                        nmr[stx] = nmr[stx] * f + ns;
                        mrun[stx] = newm;
                    }
                }
#pragma unroll
                for (int x = 0; x < 32; x++) { S[x] = 0.f; U[x] = 0.f; }
            }
        }
        if (st < 31) CP_WAIT0();
        __syncthreads();
    }

    if ((lane & 3) == 0) {
#pragma unroll
        for (int m = 0; m < 2; m++)
#pragma unroll
            for (int h = 0; h < 2; h++) {
                int rl = (wi * 2 + m) * 16 + (lane >> 2) + h * 8;
                int stx = m * 2 + h;
                sM[wj][rl] = mrun[stx];
                sD[wj][rl] = dnr[stx];
                sN[wj][rl] = nmr[stx];
            }
    }
    __syncthreads();
    if (tid < 64) {
        float mm = -1e30f;
#pragma unroll
        for (int c = 0; c < 4; c++) mm = fmaxf(mm, sM[c][tid]);
        float dn = 0.f, nm = 0.f;
#pragma unroll
        for (int c = 0; c < 4; c++) {
            float f = __expf(sM[c][tid] - mm);
            dn += sD[c][tid] * f;
            nm += sN[c][tid] * f;
        }
        out[b * NL + l0 + tid] = nm / dn + bias[l0 + tid];
    }
}

extern "C" void kernel_launch(void* const* d_in, const int* in_sizes, int n_in,
                              void* d_out, int out_size) {
    const float* X       = (const float*)d_in[0];
    const int*   mask    = (const int*)  d_in[1];
    const float* queries = (const float*)d_in[2];
    const float* Wk      = (const float*)d_in[3];
    const float* Wv      = (const float*)d_in[4];
    const float* outw    = (const float*)d_in[5];
    const float* bias    = (const float*)d_in[6];
    float* out = (float*)d_out;

    cudaFuncSetAttribute(split_x, cudaFuncAttributeMaxDynamicSharedMemorySize, 32768);
    split_x<<<512, 256, 32768>>>(X);
    dim3 gw((ND * NH / 4 + 255) / 256, 2);
    split_w<<<gw, 256>>>(Wk, Wv);
    split_qw<<<512, 256>>>(queries, outw);

    cudaFuncSetAttribute(kv_mma, cudaFuncAttributeMaxDynamicSharedMemorySize, 32768);
    dim3 g1(64, 4);
    kv_mma<<<g1, 512, 32768>>>(0);

    cudaFuncSetAttribute(attn_kernel, cudaFuncAttributeMaxDynamicSharedMemorySize, 49152);
    dim3 g2(128, 16);
    attn_kernel<<<g2, 256, 49152>>>(bias, mask, out);
}

// round 15
// speedup vs baseline: 1.3407x; 1.0160x over previous
#include <cuda_runtime.h>
#include <cuda_bf16.h>
#include <cuda_fp16.h>
#include <cstdint>
#include <math.h>

#define NB 16
#define NT 512
#define NH 1024
#define NL 8192
#define ND 256

typedef unsigned int u32;

// ---- attn operands: single fp16, mma.sync fragment order ----
__device__ uint4 g_Qf[NL * ND / 8];
__device__ uint4 g_Wf[NL * ND / 8];
__device__ uint2 g_Kf[NB * NT * ND / 4];
__device__ uint2 g_Vf[NB * NT * ND / 4];

// ---- kv-gemm operands: single fp16 ----
__device__ uint4 g_Xf[NB * NT * NH / 8];
__device__ uint2 g_Wkf[ND * NH / 4];
__device__ uint2 g_Wvf[ND * NH / 4];

__device__ __forceinline__ void mma_f16(float* c, const uint4& a, const uint2& b) {
    asm("mma.sync.aligned.m16n8k16.row.col.f32.f16.f16.f32 "
        "{%0,%1,%2,%3}, {%4,%5,%6,%7}, {%8,%9}, {%0,%1,%2,%3};"
        : "+f"(c[0]), "+f"(c[1]), "+f"(c[2]), "+f"(c[3])
        : "r"(a.x), "r"(a.y), "r"(a.z), "r"(a.w), "r"(b.x), "r"(b.y));
}
__device__ __forceinline__ u32 h2pair(float x0, float x1) {
    __half2 h = __floats2half2_rn(x0, x1);
    return *(u32*)&h;
}
__device__ __forceinline__ u32 smem_u32(const void* p) {
    u32 a; asm("{ .reg .u64 t; cvta.to.shared.u64 t, %1; cvt.u32.u64 %0, t; }" : "=r"(a) : "l"(p));
    return a;
}
__device__ __forceinline__ void cpasync16(u32 dst, const void* src) {
    asm volatile("cp.async.cg.shared.global [%0], [%1], 16;" :: "r"(dst), "l"(src));
}
#define CP_COMMIT() asm volatile("cp.async.commit_group;" ::: "memory")
#define CP_WAIT0()  asm volatile("cp.async.wait_group 0;" ::: "memory")

// ---------------------------------------------------------------------------
// split_x: X fp32 -> Xf single fp16 A-frag order, smem-staged. (proven)
// ---------------------------------------------------------------------------
__global__ __launch_bounds__(256, 1) void split_x(const float* __restrict__ X) {
    extern __shared__ u32 s[];
    const int mt  = blockIdx.x;
    const int tid = threadIdx.x;

#pragma unroll 4
    for (int it = 0; it < 16; it++) {
        int i  = tid + it * 256;
        int r  = i >> 8;
        int c4 = i & 255;
        float4 x = *(const float4*)&X[((size_t)mt * 16 + r) * NH + c4 * 4];
        float xa[4] = {x.x, x.y, x.z, x.w};
        int rh = r >> 3, lane_lo = (r & 7) * 4;
#pragma unroll
        for (int p = 0; p < 2; p++) {
            int d = c4 * 4 + p * 2;
            int kt = d >> 4, kd = d & 15;
            int lane = lane_lo + ((kd >> 1) & 3);
            int idx = (kt * 32 + lane) * 4 + ((kd >> 3) * 2 + rh);
            s[idx] = h2pair(xa[p * 2], xa[p * 2 + 1]);
        }
    }
    __syncthreads();
    uint4* o = g_Xf + (size_t)mt * 2048;
    const uint4* s4 = (const uint4*)s;
#pragma unroll
    for (int it = 0; it < 8; it++)
        o[tid + it * 256] = s4[tid + it * 256];
}

// ---------------------------------------------------------------------------
// split_qw: queries (scale folded) / out_weight -> fp16 A-frags, staged (proven)
// ---------------------------------------------------------------------------
__global__ __launch_bounds__(256, 1) void split_qw(
    const float* __restrict__ Q, const float* __restrict__ W)
{
    __shared__ u32 s[2 * 2048];
    const int mt  = blockIdx.x;
    const int tid = threadIdx.x;
    const float sc = 0.0625f;

#pragma unroll 2
    for (int it = 0; it < 4; it++) {
        int i  = tid + it * 256;
        int r  = i >> 6;
        int c4 = i & 63;
        float4 q = *(const float4*)&Q[((size_t)mt * 16 + r) * ND + c4 * 4];
        float4 w = *(const float4*)&W[((size_t)mt * 16 + r) * ND + c4 * 4];
        float qa[4] = {q.x * sc, q.y * sc, q.z * sc, q.w * sc};
        float wa[4] = {w.x, w.y, w.z, w.w};
        int rh = r >> 3, lane_lo = (r & 7) * 4;
#pragma unroll
        for (int p = 0; p < 2; p++) {
            int d = c4 * 4 + p * 2;
            int kt = d >> 4, kd = d & 15;
            int lane = lane_lo + ((kd >> 1) & 3);
            int idx = (kt * 32 + lane) * 4 + ((kd >> 3) * 2 + rh);
            s[idx]        = h2pair(qa[p * 2], qa[p * 2 + 1]);
            s[2048 + idx] = h2pair(wa[p * 2], wa[p * 2 + 1]);
        }
    }
    __syncthreads();
    const uint4* s4 = (const uint4*)s;
    uint4* oq = g_Qf + (size_t)mt * 512;
    uint4* ow = g_Wf + (size_t)mt * 512;
    oq[tid]       = s4[tid];
    oq[tid + 256] = s4[tid + 256];
    ow[tid]       = s4[512 + tid];
    ow[tid + 256] = s4[512 + tid + 256];
}

// ---------------------------------------------------------------------------
// split_w: Wk/Wv fp32 [256,1024] -> single fp16 B-frag order (proven)
// ---------------------------------------------------------------------------
__global__ void split_w(const float* __restrict__ Wk, const float* __restrict__ Wv) {
    int i = blockIdx.x * blockDim.x + threadIdx.x;
    if (i >= ND * NH / 4) return;
    const float* src = blockIdx.y ? Wv : Wk;
    u32* dst = (u32*)(blockIdx.y ? g_Wvf : g_Wkf);
    int d  = i >> 8;
    int h0 = (i & 255) * 4;
    float4 x = ((const float4*)src)[i];
    float xa[4] = {x.x, x.y, x.z, x.w};
    int nt = d >> 3, nr = d & 7;
#pragma unroll
    for (int p = 0; p < 2; p++) {
        int h  = h0 + p * 2;
        int kt = h >> 4, kd = h & 15;
        int lane = nr * 4 + ((kd >> 1) & 3);
        size_t idx = (((size_t)nt * 64 + kt) * 32 + lane) * 2 + (kd >> 3);
        dst[idx] = h2pair(xa[p * 2], xa[p * 2 + 1]);
    }
}

// ---------------------------------------------------------------------------
// kv_mma: K/V projection, single fp16, OCCUPANCY 2.
// CTA tile = 64 bt rows x 128 n. grid (128, 4): bx = bt tile, by = ng.
// 256 threads, 8 warps: wm = w>>1 (1 mt = 16 rows), wt = w&1 (8 nt = 64 cols).
// Slab per kt (6KB): Xf 0 (2KB: 4mt x 32 x 16B) | Wf 2048 (4KB: 16nt x 32 x 8B).
// 2 kt/stage, double buffer = 24KB dyn smem -> 2 CTAs/SM.
// ---------------------------------------------------------------------------
__global__ __launch_bounds__(256, 2) void kv_mma(int dummy) {
    extern __shared__ __align__(16) char dsm[];
    const int tid  = threadIdx.x;
    const int lane = tid & 31;
    const int w    = tid >> 5;
    const int wm   = w >> 1;            // 0..3: mt within CTA
    const int wt   = w & 1;             // 0..1: n half (8 nt each)
    const int ng   = blockIdx.y;
    const int isV  = ng >> 1;
    const int nhalf = ng & 1;
    const u32 smb  = smem_u32(dsm);

    const uint4* Bsrc = (const uint4*)(isV ? g_Wvf : g_Wkf);
    u32* dst = (u32*)(isV ? g_Vf : g_Kf);

    const size_t aRow = (size_t)blockIdx.x * 4;   // mt base (4 mt per CTA)
    const size_t ntBase = (size_t)nhalf * 16;

    float acc[32];
#pragma unroll
    for (int x = 0; x < 32; x++) acc[x] = 0.f;

    auto loadStage = [&](int buf, int kt0) {
#pragma unroll
        for (int s = 0; s < 2; s++) {
            int kt = kt0 + s;
            u32 base = smb + buf * 12288 + s * 6144;
#pragma unroll
            for (int r = 0; r < 2; r++) {
                int idx = tid + r * 256;          // 0..511; 384 useful
                if (idx < 128) {
                    int mt = idx >> 5, ln = idx & 31;
                    cpasync16(base + idx * 16,
                              g_Xf + ((aRow + mt) * 64 + kt) * 32 + ln);
                } else if (idx < 384) {
                    int i2 = idx - 128;            // 0..255
                    int nt = i2 >> 4, lp = i2 & 15;
                    cpasync16(base + 2048 + i2 * 16,
                              Bsrc + ((ntBase + nt) * 64 + kt) * 16 + lp);
                }
            }
        }
        CP_COMMIT();
    };

    loadStage(0, 0);
    CP_WAIT0();
    __syncthreads();

    for (int st = 0; st < 32; st++) {
        const int buf = st & 1;
        if (st < 31) loadStage(buf ^ 1, (st + 1) * 2);
#pragma unroll
        for (int s = 0; s < 2; s++) {
            const char* sb = dsm + buf * 12288 + s * 6144;
            uint4 xf = *(const uint4*)(sb + (wm * 32 + lane) * 16);
            const char* bb = sb + 2048;
#pragma unroll
            for (int j = 0; j < 8; j++) {
                int nt = wt * 8 + j;
                uint2 wf = *(const uint2*)(bb + (nt * 32 + lane) * 8);
                mma_f16(&acc[j * 4], xf, wf);
            }
        }
        if (st < 31) CP_WAIT0();
        __syncthreads();
    }

    // epilogue: scatter fp16 pairs into attn B-frag layout
#pragma unroll
    for (int j = 0; j < 8; j++) {
        int d  = nhalf * 128 + wt * 64 + j * 8 + (lane & 3) * 2;
        int kt = d >> 4, kd = d & 15;
        int lane_lo = (kd >> 1) & 3;
#pragma unroll
        for (int h = 0; h < 2; h++) {
            int bt = blockIdx.x * 64 + wm * 16 + (lane >> 2) + h * 8;
            int bb2 = bt >> 9, t = bt & 511;
            int nt = t >> 3, rt = t & 7;
            size_t idx = ((((size_t)bb2 * 64 + nt) * 16 + kt) * 32 + rt * 4 + lane_lo) * 2 + (kd >> 3);
            dst[idx] = h2pair(acc[j * 4 + h * 2], acc[j * 4 + h * 2 + 1]);
        }
    }
}

// ---------------------------------------------------------------------------
// attn: unchanged from round 13/14 (occupancy 2, 64 labels x 128 T per CTA).
// ---------------------------------------------------------------------------
__global__ __launch_bounds__(256, 2) void attn_kernel(
    const float* __restrict__ bias,
    const int*   __restrict__ mask,
    float*       __restrict__ out)
{
    extern __shared__ __align__(16) char dsm[];
    __shared__ int   smask[NT];
    __shared__ float sM[4][64], sD[4][64], sN[4][64];

    const int tid  = threadIdx.x;
    const int lane = tid & 31;
    const int w    = tid >> 5;
    const int wi   = w >> 2;
    const int wj   = w & 3;
    const int l0   = blockIdx.x * 64;
    const int b    = blockIdx.y;
    const u32 smb  = smem_u32(dsm);

    smask[tid]       = mask[b * NT + tid];
    smask[tid + 256] = mask[b * NT + tid + 256];

    const size_t aRow = (size_t)blockIdx.x * 4;

    auto loadStage = [&](int buf, int g0) {
#pragma unroll
        for (int s = 0; s < 2; s++) {
            int g  = g0 + s;
            int kt = g & 15;
            size_t bRow = (size_t)b * 64 + (g >> 4) * 16;
            u32 base = smb + buf * 24576 + s * 12288;
#pragma unroll
            for (int r = 0; r < 3; r++) {
                int idx = tid + r * 256;
                if (idx < 256) {
                    int arr = idx >> 7, el = idx & 127;
                    int mt = el >> 5, ln = el & 31;
                    const uint4* src = arr ? g_Wf : g_Qf;
                    cpasync16(base + idx * 16,
                              src + ((aRow + mt) * 16 + kt) * 32 + ln);
                } else {
                    int i2 = idx - 256;
                    int arr = i2 >> 8, be = i2 & 255;
                    int nt = be >> 4, lp = be & 15;
                    const uint4* src = (const uint4*)(arr ? g_Vf : g_Kf);
                    cpasync16(base + 4096 + i2 * 16,
                              src + ((bRow + nt) * 16 + kt) * 16 + lp);
                }
            }
        }
        CP_COMMIT();
    };

    float S[32], U[32];
#pragma unroll
    for (int x = 0; x < 32; x++) { S[x] = 0.f; U[x] = 0.f; }
    float mrun[4], dnr[4], nmr[4];
#pragma unroll
    for (int x = 0; x < 4; x++) { mrun[x] = -1e30f; dnr[x] = 0.f; nmr[x] = 0.f; }

    loadStage(0, 0);
    CP_WAIT0();
    __syncthreads();

    for (int st = 0; st < 32; st++) {
        const int buf = st & 1;
        if (st < 31) loadStage(buf ^ 1, (st + 1) * 2);
#pragma unroll
        for (int s = 0; s < 2; s++) {
            const int g = st * 2 + s;
            const char* sb = dsm + buf * 24576 + s * 12288;
            uint4 qf[2], wf[2];
#pragma unroll
            for (int m = 0; m < 2; m++) {
                int mt = wi * 2 + m;
                qf[m] = *(const uint4*)(sb +        (mt * 32 + lane) * 16);
                wf[m] = *(const uint4*)(sb + 2048 + (mt * 32 + lane) * 16);
            }
#pragma unroll
            for (int j = 0; j < 4; j++) {
                int nt = wj * 4 + j;
                uint2 kf = *(const uint2*)(sb + 4096 + (nt * 32 + lane) * 8);
                uint2 vf = *(const uint2*)(sb + 8192 + (nt * 32 + lane) * 8);
#pragma unroll
                for (int m = 0; m < 2; m++) {
                    mma_f16(&S[(m * 4 + j) * 4], qf[m], kf);
                    mma_f16(&U[(m * 4 + j) * 4], wf[m], vf);
                }
            }

            if ((g & 15) == 15) {
                const int chunk = g >> 4;
                const int cb = chunk * 128 + wj * 32 + (lane & 3) * 2;
#pragma unroll
                for (int m = 0; m < 2; m++) {
#pragma unroll
                    for (int h = 0; h < 2; h++) {
                        int stx = m * 2 + h;
                        float mloc = -1e30f;
                        int   mk[8];
                        float sv[8];
#pragma unroll
                        for (int j = 0; j < 4; j++)
#pragma unroll
                            for (int e = 0; e < 2; e++) {
                                int ix = j * 2 + e;
                                mk[ix] = smask[cb + j * 8 + e];
                                sv[ix] = S[(m * 4 + j) * 4 + h * 2 + e];
                                if (mk[ix]) mloc = fmaxf(mloc, sv[ix]);
                            }
                        mloc = fmaxf(mloc, __shfl_xor_sync(0xFFFFFFFFu, mloc, 1));
                        mloc = fmaxf(mloc, __shfl_xor_sync(0xFFFFFFFFu, mloc, 2));
                        float newm = fmaxf(mrun[stx], mloc);
                        float f = __expf(mrun[stx] - newm);
                        float ds = 0.f, ns = 0.f;
#pragma unroll
                        for (int j = 0; j < 4; j++)
#pragma unroll
                            for (int e = 0; e < 2; e++) {
                                int ix = j * 2 + e;
                                float p = mk[ix] ? __expf(sv[ix] - newm) : 0.f;
                                ds += p;
                                ns += p * U[(m * 4 + j) * 4 + h * 2 + e];
                            }
                        ds += __shfl_xor_sync(0xFFFFFFFFu, ds, 1);
                        ds += __shfl_xor_sync(0xFFFFFFFFu, ds, 2);
                        ns += __shfl_xor_sync(0xFFFFFFFFu, ns, 1);
                        ns += __shfl_xor_sync(0xFFFFFFFFu, ns, 2);
                        dnr[stx] = dnr[stx] * f + ds;
                        nmr[stx] = nmr[stx] * f + ns;
                        mrun[stx] = newm;
                    }
                }
#pragma unroll
                for (int x = 0; x < 32; x++) { S[x] = 0.f; U[x] = 0.f; }
            }
        }
        if (st < 31) CP_WAIT0();
        __syncthreads();
    }

    if ((lane & 3) == 0) {
#pragma unroll
        for (int m = 0; m < 2; m++)
#pragma unroll
            for (int h = 0; h < 2; h++) {
                int rl = (wi * 2 + m) * 16 + (lane >> 2) + h * 8;
                int stx = m * 2 + h;
                sM[wj][rl] = mrun[stx];
                sD[wj][rl] = dnr[stx];
                sN[wj][rl] = nmr[stx];
            }
    }
    __syncthreads();
    if (tid < 64) {
        float mm = -1e30f;
#pragma unroll
        for (int c = 0; c < 4; c++) mm = fmaxf(mm, sM[c][tid]);
        float dn = 0.f, nm = 0.f;
#pragma unroll
        for (int c = 0; c < 4; c++) {
            float f = __expf(sM[c][tid] - mm);
            dn += sD[c][tid] * f;
            nm += sN[c][tid] * f;
        }
        out[b * NL + l0 + tid] = nm / dn + bias[l0 + tid];
    }
}

extern "C" void kernel_launch(void* const* d_in, const int* in_sizes, int n_in,
                              void* d_out, int out_size) {
    const float* X       = (const float*)d_in[0];
    const int*   mask    = (const int*)  d_in[1];
    const float* queries = (const float*)d_in[2];
    const float* Wk      = (const float*)d_in[3];
    const float* Wv      = (const float*)d_in[4];
    const float* outw    = (const float*)d_in[5];
    const float* bias    = (const float*)d_in[6];
    float* out = (float*)d_out;

    cudaFuncSetAttribute(split_x, cudaFuncAttributeMaxDynamicSharedMemorySize, 32768);
    split_x<<<512, 256, 32768>>>(X);
    dim3 gw((ND * NH / 4 + 255) / 256, 2);
    split_w<<<gw, 256>>>(Wk, Wv);
    split_qw<<<512, 256>>>(queries, outw);

    cudaFuncSetAttribute(kv_mma, cudaFuncAttributeMaxDynamicSharedMemorySize, 24576);
    dim3 g1(128, 4);
    kv_mma<<<g1, 256, 24576>>>(0);

    cudaFuncSetAttribute(attn_kernel, cudaFuncAttributeMaxDynamicSharedMemorySize, 49152);
    dim3 g2(128, 16);
    attn_kernel<<<g2, 256, 49152>>>(bias, mask, out);
}

// round 17
// speedup vs baseline: 1.3780x; 1.0278x over previous
#include <cuda_runtime.h>
#include <cuda_bf16.h>
#include <cuda_fp16.h>
#include <cstdint>
#include <math.h>

#define NB 16
#define NT 512
#define NH 1024
#define NL 8192
#define ND 256

typedef unsigned int u32;

// ---- attn operands: single fp16, mma.sync fragment order ----
__device__ uint4 g_Qf[NL * ND / 8];
__device__ uint4 g_Wf[NL * ND / 8];
__device__ uint2 g_Kf[NB * NT * ND / 4];
__device__ uint2 g_Vf[NB * NT * ND / 4];

// ---- kv-gemm operands: single fp16 ----
__device__ uint4 g_Xf[NB * NT * NH / 8];
__device__ uint2 g_Wkf[ND * NH / 4];
__device__ uint2 g_Wvf[ND * NH / 4];

__device__ __forceinline__ void mma_f16(float* c, const uint4& a, const uint2& b) {
    asm("mma.sync.aligned.m16n8k16.row.col.f32.f16.f16.f32 "
        "{%0,%1,%2,%3}, {%4,%5,%6,%7}, {%8,%9}, {%0,%1,%2,%3};"
        : "+f"(c[0]), "+f"(c[1]), "+f"(c[2]), "+f"(c[3])
        : "r"(a.x), "r"(a.y), "r"(a.z), "r"(a.w), "r"(b.x), "r"(b.y));
}
__device__ __forceinline__ u32 h2pair(float x0, float x1) {
    __half2 h = __floats2half2_rn(x0, x1);
    return *(u32*)&h;
}
__device__ __forceinline__ u32 smem_u32(const void* p) {
    u32 a; asm("{ .reg .u64 t; cvta.to.shared.u64 t, %1; cvt.u32.u64 %0, t; }" : "=r"(a) : "l"(p));
    return a;
}
__device__ __forceinline__ void cpasync16(u32 dst, const void* src) {
    asm volatile("cp.async.cg.shared.global [%0], [%1], 16;" :: "r"(dst), "l"(src));
}
#define CP_COMMIT() asm volatile("cp.async.commit_group;" ::: "memory")
#define CP_WAIT0()  asm volatile("cp.async.wait_group 0;" ::: "memory")

// ---------------------------------------------------------------------------
// split_x: X fp32 -> Xf single fp16 A-frag order, smem-staged. (proven)
// ---------------------------------------------------------------------------
__global__ __launch_bounds__(256, 1) void split_x(const float* __restrict__ X) {
    extern __shared__ u32 s[];
    const int mt  = blockIdx.x;
    const int tid = threadIdx.x;

#pragma unroll 4
    for (int it = 0; it < 16; it++) {
        int i  = tid + it * 256;
        int r  = i >> 8;
        int c4 = i & 255;
        float4 x = *(const float4*)&X[((size_t)mt * 16 + r) * NH + c4 * 4];
        float xa[4] = {x.x, x.y, x.z, x.w};
        int rh = r >> 3, lane_lo = (r & 7) * 4;
#pragma unroll
        for (int p = 0; p < 2; p++) {
            int d = c4 * 4 + p * 2;
            int kt = d >> 4, kd = d & 15;
            int lane = lane_lo + ((kd >> 1) & 3);
            int idx = (kt * 32 + lane) * 4 + ((kd >> 3) * 2 + rh);
            s[idx] = h2pair(xa[p * 2], xa[p * 2 + 1]);
        }
    }
    __syncthreads();
    uint4* o = g_Xf + (size_t)mt * 2048;
    const uint4* s4 = (const uint4*)s;
#pragma unroll
    for (int it = 0; it < 8; it++)
        o[tid + it * 256] = s4[tid + it * 256];
}

// ---------------------------------------------------------------------------
// split_qw: queries (scale folded) / out_weight -> fp16 A-frags, staged (proven)
// ---------------------------------------------------------------------------
__global__ __launch_bounds__(256, 1) void split_qw(
    const float* __restrict__ Q, const float* __restrict__ W)
{
    __shared__ u32 s[2 * 2048];
    const int mt  = blockIdx.x;
    const int tid = threadIdx.x;
    const float sc = 0.0625f;

#pragma unroll 2
    for (int it = 0; it < 4; it++) {
        int i  = tid + it * 256;
        int r  = i >> 6;
        int c4 = i & 63;
        float4 q = *(const float4*)&Q[((size_t)mt * 16 + r) * ND + c4 * 4];
        float4 w = *(const float4*)&W[((size_t)mt * 16 + r) * ND + c4 * 4];
        float qa[4] = {q.x * sc, q.y * sc, q.z * sc, q.w * sc};
        float wa[4] = {w.x, w.y, w.z, w.w};
        int rh = r >> 3, lane_lo = (r & 7) * 4;
#pragma unroll
        for (int p = 0; p < 2; p++) {
            int d = c4 * 4 + p * 2;
            int kt = d >> 4, kd = d & 15;
            int lane = lane_lo + ((kd >> 1) & 3);
            int idx = (kt * 32 + lane) * 4 + ((kd >> 3) * 2 + rh);
            s[idx]        = h2pair(qa[p * 2], qa[p * 2 + 1]);
            s[2048 + idx] = h2pair(wa[p * 2], wa[p * 2 + 1]);
        }
    }
    __syncthreads();
    const uint4* s4 = (const uint4*)s;
    uint4* oq = g_Qf + (size_t)mt * 512;
    uint4* ow = g_Wf + (size_t)mt * 512;
    oq[tid]       = s4[tid];
    oq[tid + 256] = s4[tid + 256];
    ow[tid]       = s4[512 + tid];
    ow[tid + 256] = s4[512 + tid + 256];
}

// ---------------------------------------------------------------------------
// split_w: Wk/Wv fp32 [256,1024] -> single fp16 B-frag order (proven)
// ---------------------------------------------------------------------------
__global__ void split_w(const float* __restrict__ Wk, const float* __restrict__ Wv) {
    int i = blockIdx.x * blockDim.x + threadIdx.x;
    if (i >= ND * NH / 4) return;
    const float* src = blockIdx.y ? Wv : Wk;
    u32* dst = (u32*)(blockIdx.y ? g_Wvf : g_Wkf);
    int d  = i >> 8;
    int h0 = (i & 255) * 4;
    float4 x = ((const float4*)src)[i];
    float xa[4] = {x.x, x.y, x.z, x.w};
    int nt = d >> 3, nr = d & 7;
#pragma unroll
    for (int p = 0; p < 2; p++) {
        int h  = h0 + p * 2;
        int kt = h >> 4, kd = h & 15;
        int lane = nr * 4 + ((kd >> 1) & 3);
        size_t idx = (((size_t)nt * 64 + kt) * 32 + lane) * 2 + (kd >> 3);
        dst[idx] = h2pair(xa[p * 2], xa[p * 2 + 1]);
    }
}

// ---------------------------------------------------------------------------
// kv_mma: K/V projection, single fp16, OCCUPANCY 2, SINGLE WAVE.
// CTA tile = 128 bt rows x 128 n. grid (64, 4) = 256 CTAs <= 296 slots.
// 256 threads, 8 warps: wi = w>>1 (2 mt each), wj = w&1 (8 nt each).
// Slab per kt (8KB): Xf 0 (4KB: 8mt x 32 x 16B) | Wf 4096 (4KB: 16nt x 32 x 8B).
// 2 kt/stage, double buffer = 32KB dyn smem -> 2 CTAs/SM.
// ---------------------------------------------------------------------------
__global__ __launch_bounds__(256, 2) void kv_mma(int dummy) {
    extern __shared__ __align__(16) char dsm[];
    const int tid  = threadIdx.x;
    const int lane = tid & 31;
    const int w    = tid >> 5;
    const int wi   = w >> 1;            // 0..3: 2 mt each
    const int wj   = w & 1;             // 0..1: 8 nt each
    const int ng   = blockIdx.y;
    const int isV  = ng >> 1;
    const int nhalf = ng & 1;
    const u32 smb  = smem_u32(dsm);

    const uint4* Bsrc = (const uint4*)(isV ? g_Wvf : g_Wkf);
    u32* dst = (u32*)(isV ? g_Vf : g_Kf);

    const size_t aRow = (size_t)blockIdx.x * 8;   // mt base (8 mt per CTA)
    const size_t ntBase = (size_t)nhalf * 16;

    float acc[64];                      // [(m*8+j)*4 + c], m in 0..1, j in 0..7
#pragma unroll
    for (int x = 0; x < 64; x++) acc[x] = 0.f;

    auto loadStage = [&](int buf, int kt0) {
#pragma unroll
        for (int s = 0; s < 2; s++) {
            int kt = kt0 + s;
            u32 base = smb + buf * 16384 + s * 8192;
#pragma unroll
            for (int r = 0; r < 2; r++) {
                int idx = tid + r * 256;          // 0..511
                if (idx < 256) {
                    int mt = idx >> 5, ln = idx & 31;
                    cpasync16(base + idx * 16,
                              g_Xf + ((aRow + mt) * 64 + kt) * 32 + ln);
                } else {
                    int i2 = idx - 256;            // 0..255
                    int nt = i2 >> 4, lp = i2 & 15;
                    cpasync16(base + 4096 + i2 * 16,
                              Bsrc + ((ntBase + nt) * 64 + kt) * 16 + lp);
                }
            }
        }
        CP_COMMIT();
    };

    loadStage(0, 0);
    CP_WAIT0();
    __syncthreads();

    for (int st = 0; st < 32; st++) {
        const int buf = st & 1;
        if (st < 31) loadStage(buf ^ 1, (st + 1) * 2);
#pragma unroll
        for (int s = 0; s < 2; s++) {
            const char* sb = dsm + buf * 16384 + s * 8192;
            uint4 xf[2];
#pragma unroll
            for (int m = 0; m < 2; m++)
                xf[m] = *(const uint4*)(sb + ((wi * 2 + m) * 32 + lane) * 16);
            const char* bb = sb + 4096;
#pragma unroll
            for (int j = 0; j < 8; j++) {
                int nt = wj * 8 + j;
                uint2 wf = *(const uint2*)(bb + (nt * 32 + lane) * 8);
#pragma unroll
                for (int m = 0; m < 2; m++)
                    mma_f16(&acc[(m * 8 + j) * 4], xf[m], wf);
            }
        }
        if (st < 31) CP_WAIT0();
        __syncthreads();
    }

    // epilogue: scatter fp16 pairs into attn B-frag layout
#pragma unroll
    for (int j = 0; j < 8; j++) {
        int d  = nhalf * 128 + wj * 64 + j * 8 + (lane & 3) * 2;
        int kt = d >> 4, kd = d & 15;
        int lane_lo = (kd >> 1) & 3;
#pragma unroll
        for (int m = 0; m < 2; m++) {
#pragma unroll
            for (int h = 0; h < 2; h++) {
                int bt = blockIdx.x * 128 + (wi * 2 + m) * 16 + (lane >> 2) + h * 8;
                int bb2 = bt >> 9, t = bt & 511;
                int nt = t >> 3, rt = t & 7;
                size_t idx = ((((size_t)bb2 * 64 + nt) * 16 + kt) * 32 + rt * 4 + lane_lo) * 2 + (kd >> 3);
                dst[idx] = h2pair(acc[(m * 8 + j) * 4 + h * 2],
                                  acc[(m * 8 + j) * 4 + h * 2 + 1]);
            }
        }
    }
}

// ---------------------------------------------------------------------------
// attn: unchanged (occupancy 2, 64 labels x 128 T per CTA, at fp16 issue floor).
// ---------------------------------------------------------------------------
__global__ __launch_bounds__(256, 2) void attn_kernel(
    const float* __restrict__ bias,
    const int*   __restrict__ mask,
    float*       __restrict__ out)
{
    extern __shared__ __align__(16) char dsm[];
    __shared__ int   smask[NT];
    __shared__ float sM[4][64], sD[4][64], sN[4][64];

    const int tid  = threadIdx.x;
    const int lane = tid & 31;
    const int w    = tid >> 5;
    const int wi   = w >> 2;
    const int wj   = w & 3;
    const int l0   = blockIdx.x * 64;
    const int b    = blockIdx.y;
    const u32 smb  = smem_u32(dsm);

    smask[tid]       = mask[b * NT + tid];
    smask[tid + 256] = mask[b * NT + tid + 256];

    const size_t aRow = (size_t)blockIdx.x * 4;

    auto loadStage = [&](int buf, int g0) {
#pragma unroll
        for (int s = 0; s < 2; s++) {
            int g  = g0 + s;
            int kt = g & 15;
            size_t bRow = (size_t)b * 64 + (g >> 4) * 16;
            u32 base = smb + buf * 24576 + s * 12288;
#pragma unroll
            for (int r = 0; r < 3; r++) {
                int idx = tid + r * 256;
                if (idx < 256) {
                    int arr = idx >> 7, el = idx & 127;
                    int mt = el >> 5, ln = el & 31;
                    const uint4* src = arr ? g_Wf : g_Qf;
                    cpasync16(base + idx * 16,
                              src + ((aRow + mt) * 16 + kt) * 32 + ln);
                } else {
                    int i2 = idx - 256;
                    int arr = i2 >> 8, be = i2 & 255;
                    int nt = be >> 4, lp = be & 15;
                    const uint4* src = (const uint4*)(arr ? g_Vf : g_Kf);
                    cpasync16(base + 4096 + i2 * 16,
                              src + ((bRow + nt) * 16 + kt) * 16 + lp);
                }
            }
        }
        CP_COMMIT();
    };

    float S[32], U[32];
#pragma unroll
    for (int x = 0; x < 32; x++) { S[x] = 0.f; U[x] = 0.f; }
    float mrun[4], dnr[4], nmr[4];
#pragma unroll
    for (int x = 0; x < 4; x++) { mrun[x] = -1e30f; dnr[x] = 0.f; nmr[x] = 0.f; }

    loadStage(0, 0);
    CP_WAIT0();
    __syncthreads();

    for (int st = 0; st < 32; st++) {
        const int buf = st & 1;
        if (st < 31) loadStage(buf ^ 1, (st + 1) * 2);
#pragma unroll
        for (int s = 0; s < 2; s++) {
            const int g = st * 2 + s;
            const char* sb = dsm + buf * 24576 + s * 12288;
            uint4 qf[2], wf[2];
#pragma unroll
            for (int m = 0; m < 2; m++) {
                int mt = wi * 2 + m;
                qf[m] = *(const uint4*)(sb +        (mt * 32 + lane) * 16);
                wf[m] = *(const uint4*)(sb + 2048 + (mt * 32 + lane) * 16);
            }
#pragma unroll
            for (int j = 0; j < 4; j++) {
                int nt = wj * 4 + j;
                uint2 kf = *(const uint2*)(sb + 4096 + (nt * 32 + lane) * 8);
                uint2 vf = *(const uint2*)(sb + 8192 + (nt * 32 + lane) * 8);
#pragma unroll
                for (int m = 0; m < 2; m++) {
                    mma_f16(&S[(m * 4 + j) * 4], qf[m], kf);
                    mma_f16(&U[(m * 4 + j) * 4], wf[m], vf);
                }
            }

            if ((g & 15) == 15) {
                const int chunk = g >> 4;
                const int cb = chunk * 128 + wj * 32 + (lane & 3) * 2;
#pragma unroll
                for (int m = 0; m < 2; m++) {
#pragma unroll
                    for (int h = 0; h < 2; h++) {
                        int stx = m * 2 + h;
                        float mloc = -1e30f;
                        int   mk[8];
                        float sv[8];
#pragma unroll
                        for (int j = 0; j < 4; j++)
#pragma unroll
                            for (int e = 0; e < 2; e++) {
                                int ix = j * 2 + e;
                                mk[ix] = smask[cb + j * 8 + e];
                                sv[ix] = S[(m * 4 + j) * 4 + h * 2 + e];
                                if (mk[ix]) mloc = fmaxf(mloc, sv[ix]);
                            }
                        mloc = fmaxf(mloc, __shfl_xor_sync(0xFFFFFFFFu, mloc, 1));
                        mloc = fmaxf(mloc, __shfl_xor_sync(0xFFFFFFFFu, mloc, 2));
                        float newm = fmaxf(mrun[stx], mloc);
                        float f = __expf(mrun[stx] - newm);
                        float ds = 0.f, ns = 0.f;
#pragma unroll
                        for (int j = 0; j < 4; j++)
#pragma unroll
                            for (int e = 0; e < 2; e++) {
                                int ix = j * 2 + e;
                                float p = mk[ix] ? __expf(sv[ix] - newm) : 0.f;
                                ds += p;
                                ns += p * U[(m * 4 + j) * 4 + h * 2 + e];
                            }
                        ds += __shfl_xor_sync(0xFFFFFFFFu, ds, 1);
                        ds += __shfl_xor_sync(0xFFFFFFFFu, ds, 2);
                        ns += __shfl_xor_sync(0xFFFFFFFFu, ns, 1);
                        ns += __shfl_xor_sync(0xFFFFFFFFu, ns, 2);
                        dnr[stx] = dnr[stx] * f + ds;
                        nmr[stx] = nmr[stx] * f + ns;
                        mrun[stx] = newm;
                    }
                }
#pragma unroll
                for (int x = 0; x < 32; x++) { S[x] = 0.f; U[x] = 0.f; }
            }
        }
        if (st < 31) CP_WAIT0();
        __syncthreads();
    }

    if ((lane & 3) == 0) {
#pragma unroll
        for (int m = 0; m < 2; m++)
#pragma unroll
            for (int h = 0; h < 2; h++) {
                int rl = (wi * 2 + m) * 16 + (lane >> 2) + h * 8;
                int stx = m * 2 + h;
                sM[wj][rl] = mrun[stx];
                sD[wj][rl] = dnr[stx];
                sN[wj][rl] = nmr[stx];
            }
    }
    __syncthreads();
    if (tid < 64) {
        float mm = -1e30f;
#pragma unroll
        for (int c = 0; c < 4; c++) mm = fmaxf(mm, sM[c][tid]);
        float dn = 0.f, nm = 0.f;
#pragma unroll
        for (int c = 0; c < 4; c++) {
            float f = __expf(sM[c][tid] - mm);
            dn += sD[c][tid] * f;
            nm += sN[c][tid] * f;
        }
        out[b * NL + l0 + tid] = nm / dn + bias[l0 + tid];
    }
}

extern "C" void kernel_launch(void* const* d_in, const int* in_sizes, int n_in,
                              void* d_out, int out_size) {
    const float* X       = (const float*)d_in[0];
    const int*   mask    = (const int*)  d_in[1];
    const float* queries = (const float*)d_in[2];
    const float* Wk      = (const float*)d_in[3];
    const float* Wv      = (const float*)d_in[4];
    const float* outw    = (const float*)d_in[5];
    const float* bias    = (const float*)d_in[6];
    float* out = (float*)d_out;

    cudaFuncSetAttribute(split_x, cudaFuncAttributeMaxDynamicSharedMemorySize, 32768);
    split_x<<<512, 256, 32768>>>(X);
    dim3 gw((ND * NH / 4 + 255) / 256, 2);
    split_w<<<gw, 256>>>(Wk, Wv);
    split_qw<<<512, 256>>>(queries, outw);

    cudaFuncSetAttribute(kv_mma, cudaFuncAttributeMaxDynamicSharedMemorySize, 32768);
    dim3 g1(64, 4);
    kv_mma<<<g1, 256, 32768>>>(0);

    cudaFuncSetAttribute(attn_kernel, cudaFuncAttributeMaxDynamicSharedMemorySize, 49152);
    dim3 g2(128, 16);
    attn_kernel<<<g2, 256, 49152>>>(bias, mask, out);
}